// round 5
// baseline (speedup 1.0000x reference)
#include <cuda_runtime.h>

// LIF membrane update:
//   v_new[b,n] = ALPHA*v[b,n] + sum_i x[b,i,n]*w[i,n] - V_TH*z[b,n]
//   z_new[b,n] = (v_new[b,n] - V_TH > 0) ? 1 : 0
// Shapes: x[128,1024,512], w[1024,512], v[128,512], z[128,512]
//
// LTS-cap fix: each thread processes 4 batches per w-load, cutting w's L2
// traffic 4x (512MB total L2 touch -> ~330MB) so DRAM becomes the binder.
// Grid = 32 bgroups x 4 ntiles x 4 islices = 512 blocks (single wave).
// Cross-block i-reduction via L2-resident partials + atomic-counter "last
// block does the epilogue" (no second kernel launch).

#define B_     128
#define N_IN_  1024
#define NN_    512
#define NN4_   (NN_ / 4)              // 128 float4 per n-row
#define ALPHA_ 0.995f
#define V_TH_  2.0f

#define WARPS    8
#define THREADS  (WARPS * 32)         // 256
#define ISLICES  4
#define IWARP    (N_IN_ / ISLICES / WARPS)   // 32 i-rows per warp
#define BPER     4                    // batches per thread
#define NGROUPS  (B_ / BPER * 4)      // 128 (bgroup,ntile) output groups

#define XSTR   ((size_t)N_IN_ * NN4_) // per-batch float4 stride (131072)

// partials: [group(128)][islice(4)][bb(4)][lane(32)] float4 = 1 MB
__device__ float4 g_partial[NGROUPS * ISLICES * BPER * 32];
__device__ int    g_cnt[NGROUPS];     // zero-initialized; reset by last block

__global__ __launch_bounds__(THREADS, 4)
void lif_kernel(const float4* __restrict__ x,
                const float4* __restrict__ w,
                const float4* __restrict__ v,
                const float4* __restrict__ z,
                float4* __restrict__ out)
{
    __shared__ float4 red[WARPS][BPER][32];   // 16 KB
    __shared__ int s_last;

    const int bx   = blockIdx.x;
    const int sl   = bx & 3;               // i-slice
    const int nt   = (bx >> 2) & 3;        // n-tile
    const int bg   = bx >> 4;              // batch group (4 batches)
    const int lane = threadIdx.x & 31;
    const int wid  = threadIdx.x >> 5;

    const int n4    = nt * 32 + lane;
    const int i0    = sl * (N_IN_ / ISLICES) + wid * IWARP;
    const int b0    = bg * BPER;
    const int group = bg * 4 + nt;

    const float4* xb = x + ((size_t)b0 * N_IN_ + i0) * NN4_ + n4;
    const float4* wb = w + (size_t)i0 * NN4_ + n4;

    float4 a0 = make_float4(0.f,0.f,0.f,0.f);
    float4 a1 = a0, a2 = a0, a3 = a0;

    #pragma unroll 4
    for (int i = 0; i < IWARP; ++i) {
        const size_t r = (size_t)i * NN4_;
        float4 x0 = __ldcs(&xb[r]);
        float4 x1 = __ldcs(&xb[r +     XSTR]);
        float4 x2 = __ldcs(&xb[r + 2 * XSTR]);
        float4 x3 = __ldcs(&xb[r + 3 * XSTR]);
        float4 wv = __ldg (&wb[r]);

        a0.x += x0.x * wv.x; a0.y += x0.y * wv.y;
        a0.z += x0.z * wv.z; a0.w += x0.w * wv.w;
        a1.x += x1.x * wv.x; a1.y += x1.y * wv.y;
        a1.z += x1.z * wv.z; a1.w += x1.w * wv.w;
        a2.x += x2.x * wv.x; a2.y += x2.y * wv.y;
        a2.z += x2.z * wv.z; a2.w += x2.w * wv.w;
        a3.x += x3.x * wv.x; a3.y += x3.y * wv.y;
        a3.z += x3.z * wv.z; a3.w += x3.w * wv.w;
    }

    red[wid][0][lane] = a0;
    red[wid][1][lane] = a1;
    red[wid][2][lane] = a2;
    red[wid][3][lane] = a3;
    __syncthreads();

    // intra-block reduce over 8 warps -> partial for this i-slice
    if (threadIdx.x < BPER * 32) {
        const int bb = threadIdx.x >> 5;
        float4 s = red[0][bb][lane];
        #pragma unroll
        for (int k = 1; k < WARPS; ++k) {
            float4 t = red[k][bb][lane];
            s.x += t.x; s.y += t.y; s.z += t.z; s.w += t.w;
        }
        g_partial[(((size_t)group * ISLICES + sl) * BPER + bb) * 32 + lane] = s;
    }

    // last i-slice block of this group finishes the reduction + epilogue
    __threadfence();
    if (threadIdx.x == 0)
        s_last = (atomicAdd(&g_cnt[group], 1) == ISLICES - 1);
    __syncthreads();

    if (s_last) {
        if (threadIdx.x < BPER * 32) {
            const int bb = threadIdx.x >> 5;
            float4 sum = make_float4(0.f,0.f,0.f,0.f);
            #pragma unroll
            for (int s2 = 0; s2 < ISLICES; ++s2) {
                float4 p = g_partial[(((size_t)group * ISLICES + s2) * BPER + bb) * 32 + lane];
                sum.x += p.x; sum.y += p.y; sum.z += p.z; sum.w += p.w;
            }

            const int b  = b0 + bb;
            const int on = b * NN4_ + n4;
            float4 vv = v[on];
            float4 zz = z[on];

            float4 vn;
            vn.x = ALPHA_ * vv.x + sum.x - V_TH_ * zz.x;
            vn.y = ALPHA_ * vv.y + sum.y - V_TH_ * zz.y;
            vn.z = ALPHA_ * vv.z + sum.z - V_TH_ * zz.z;
            vn.w = ALPHA_ * vv.w + sum.w - V_TH_ * zz.w;

            float4 zn;
            zn.x = (vn.x - V_TH_ > 0.f) ? 1.f : 0.f;
            zn.y = (vn.y - V_TH_ > 0.f) ? 1.f : 0.f;
            zn.z = (vn.z - V_TH_ > 0.f) ? 1.f : 0.f;
            zn.w = (vn.w - V_TH_ > 0.f) ? 1.f : 0.f;

            out[on] = vn;                 // v_new: first B*NN floats
            out[B_ * NN4_ + on] = zn;     // z_new: next B*NN floats
        }
        if (threadIdx.x == 0)
            g_cnt[group] = 0;             // reset for next graph replay
    }
}

extern "C" void kernel_launch(void* const* d_in, const int* in_sizes, int n_in,
                              void* d_out, int out_size)
{
    const float4* x = (const float4*)d_in[0];  // [128,1024,512] f32
    const float4* w = (const float4*)d_in[1];  // [1024,512]     f32
    const float4* v = (const float4*)d_in[2];  // [128,512]      f32
    const float4* z = (const float4*)d_in[3];  // [128,512]      f32
    float4* out = (float4*)d_out;              // [2,128,512]    f32

    (void)in_sizes; (void)n_in; (void)out_size;

    lif_kernel<<<(B_ / BPER) * 4 * ISLICES, THREADS>>>(x, w, v, z, out);
}